// round 1
// baseline (speedup 1.0000x reference)
#include <cuda_runtime.h>
#include <cstdint>
#include <cstddef>

#define B_ 256
#define T_ 2048
#define I_ 128
#define H_ 64
#define G_ 256          // 4*H
#define M_ (B_*T_)      // 524288

// Scratch (device globals: allocation-free rule)
__device__ float g_pre[(size_t)M_ * G_];   // 512 MB
__device__ float g_h0 [(size_t)M_ * H_];   // 128 MB
__device__ float g_h1 [(size_t)M_ * H_];   // 128 MB

// ---------------------------------------------------------------- helpers
__device__ __forceinline__ float to_tf32(float x){
    unsigned u; asm("cvt.rna.tf32.f32 %0, %1;" : "=r"(u) : "f"(x));
    return __uint_as_float(u);
}

__device__ __forceinline__ void mma_tf32(float c[4], const unsigned a[4],
                                         unsigned b0, unsigned b1){
    asm volatile("mma.sync.aligned.m16n8k8.row.col.f32.tf32.tf32.f32 "
        "{%0,%1,%2,%3},{%4,%5,%6,%7},{%8,%9},{%0,%1,%2,%3};"
        : "+f"(c[0]),"+f"(c[1]),"+f"(c[2]),"+f"(c[3])
        : "r"(a[0]),"r"(a[1]),"r"(a[2]),"r"(a[3]),"r"(b0),"r"(b1));
}

__device__ __forceinline__ float sigmoid_f(float x){
    return __fdividef(1.f, 1.f + __expf(-x));
}
__device__ __forceinline__ float tanh_f(float x){
    // tanh(x) = 1 - 2/(1+exp(2x)); stable at both tails
    return fmaf(-2.f, __fdividef(1.f, 1.f + __expf(2.f*x)), 1.f);
}

// ---------------------------------------------------------------- pre-GEMM
// pre[m, g] = sum_k A[m,k] * W[g,k] + (b_ih[g]+b_hh[g])    (tf32 tensor cores)
// A: [M_, K] row-major, W: [256, K] row-major. Block: 128 rows x 256 cols.
template<int K>
__global__ void __launch_bounds__(256,1)
gemm_pre(const float* __restrict__ A, const float* __restrict__ W,
         const float* __restrict__ b_ih, const float* __restrict__ b_hh,
         float* __restrict__ out)
{
    constexpr int BM = 128, N = G_, KP = K + 4;   // +4 pad: conflict-free frags
    extern __shared__ float sm[];
    float* As = sm;                 // BM x KP
    float* Ws = sm + BM*KP;         // N x KP
    float* bs = Ws + N*KP;          // N

    const int tid = threadIdx.x;
    const size_t m0 = (size_t)blockIdx.x * BM;

    const float4* Ag = (const float4*)(A + m0*(size_t)K);
    for (int i = tid; i < BM*K/4; i += 256){
        float4 v = Ag[i];
        int fi = i*4, row = fi / K, col = fi % K;
        *(float4*)(As + row*KP + col) =
            make_float4(to_tf32(v.x), to_tf32(v.y), to_tf32(v.z), to_tf32(v.w));
    }
    const float4* Wg = (const float4*)W;
    for (int i = tid; i < N*K/4; i += 256){
        float4 v = Wg[i];
        int fi = i*4, row = fi / K, col = fi % K;
        *(float4*)(Ws + row*KP + col) =
            make_float4(to_tf32(v.x), to_tf32(v.y), to_tf32(v.z), to_tf32(v.w));
    }
    bs[tid] = b_ih[tid] + b_hh[tid];
    __syncthreads();

    const int warp = tid >> 5, lane = tid & 31;
    const int wm = warp >> 1, wn = warp & 1;     // 4 m-groups x 2 n-halves
    const int gid = lane >> 2, tig = lane & 3;

    float c[2][16][4];
    #pragma unroll
    for (int a = 0; a < 2; a++)
        #pragma unroll
        for (int b = 0; b < 16; b++)
            #pragma unroll
            for (int d = 0; d < 4; d++) c[a][b][d] = 0.f;

    #pragma unroll
    for (int ks = 0; ks < K/8; ++ks){
        unsigned af[2][4];
        #pragma unroll
        for (int mt = 0; mt < 2; mt++){
            int r  = wm*32 + mt*16 + gid;
            int cc = ks*8 + tig;
            af[mt][0] = __float_as_uint(As[r*KP + cc]);
            af[mt][1] = __float_as_uint(As[(r+8)*KP + cc]);
            af[mt][2] = __float_as_uint(As[r*KP + cc + 4]);
            af[mt][3] = __float_as_uint(As[(r+8)*KP + cc + 4]);
        }
        #pragma unroll
        for (int nt = 0; nt < 16; nt++){
            int n  = wn*128 + nt*8 + gid;
            int kk = ks*8 + tig;
            unsigned b0 = __float_as_uint(Ws[n*KP + kk]);
            unsigned b1 = __float_as_uint(Ws[n*KP + kk + 4]);
            mma_tf32(c[0][nt], af[0], b0, b1);
            mma_tf32(c[1][nt], af[1], b0, b1);
        }
    }

    #pragma unroll
    for (int mt = 0; mt < 2; mt++){
        size_t r = m0 + wm*32 + mt*16 + gid;
        #pragma unroll
        for (int nt = 0; nt < 16; nt++){
            int col = wn*128 + nt*8 + 2*tig;
            float bb0 = bs[col], bb1 = bs[col+1];
            *(float2*)(out + r*N + col)
                = make_float2(c[mt][nt][0] + bb0, c[mt][nt][1] + bb1);
            *(float2*)(out + (r+8)*N + col)
                = make_float2(c[mt][nt][2] + bb0, c[mt][nt][3] + bb1);
        }
    }
}

// ---------------------------------------------------------------- LSTM scan
// One block = 2 batch rows (independent sequences), 256 threads = 256 gates.
// Thread g keeps w_hh[g][0..63] packed {w,w} for fma.rn.f32x2 across the row
// pair. h/c/gates live in smem; 2 barriers per step; pre prefetched 2 deep.
__global__ void __launch_bounds__(256,1)
lstm_scan(const float* __restrict__ pre, const float* __restrict__ w_hh,
          float* __restrict__ h_out)
{
    __shared__ __align__(16) float2 h_s[H_];   // (row0,row1) pairs
    __shared__ float g_s[2][G_];
    __shared__ float c_s[2][H_];

    const int tid = threadIdx.x;
    const int b0 = blockIdx.x * 2;

    if (tid < H_){ h_s[tid] = make_float2(0.f, 0.f); c_s[0][tid] = 0.f; c_s[1][tid] = 0.f; }

    // w_hh row for this gate, packed lanewise
    unsigned long long wpk[H_];
    {
        const float4* wr = (const float4*)(w_hh + tid*H_);
        #pragma unroll
        for (int k4 = 0; k4 < H_/4; k4++){
            float4 v = wr[k4];
            asm("mov.b64 %0,{%1,%1};" : "=l"(wpk[4*k4+0]) : "f"(v.x));
            asm("mov.b64 %0,{%1,%1};" : "=l"(wpk[4*k4+1]) : "f"(v.y));
            asm("mov.b64 %0,{%1,%1};" : "=l"(wpk[4*k4+2]) : "f"(v.z));
            asm("mov.b64 %0,{%1,%1};" : "=l"(wpk[4*k4+3]) : "f"(v.w));
        }
    }

    const float* p0p = pre + ((size_t)b0     * T_) * G_ + tid;
    const float* p1p = pre + ((size_t)(b0+1) * T_) * G_ + tid;
    float p0 = p0p[0],  p1 = p1p[0];     // t = 0
    float q0 = p0p[G_], q1 = p1p[G_];    // t = 1
    const int gtype = tid >> 6;          // 0,1,3: sigmoid; 2: tanh
    __syncthreads();

    for (int t = 0; t < T_; ++t){
        int tp = (t + 2 < T_) ? t + 2 : T_ - 1;
        float r0 = __ldg(p0p + (size_t)tp * G_);
        float r1 = __ldg(p1p + (size_t)tp * G_);

        // gates(row0,row1) = pre + w_hh[g] . h, packed f32x2, 2 accum chains
        unsigned long long accA, accB;
        asm("mov.b64 %0,{%1,%2};" : "=l"(accA) : "f"(p0), "f"(p1));
        asm("mov.b64 %0,{%1,%2};" : "=l"(accB) : "f"(0.f), "f"(0.f));
        const ulonglong2* hv = (const ulonglong2*)h_s;
        #pragma unroll
        for (int k2 = 0; k2 < H_/2; k2++){
            ulonglong2 hp = hv[k2];
            asm("fma.rn.f32x2 %0, %1, %2, %0;" : "+l"(accA) : "l"(wpk[2*k2]),   "l"(hp.x));
            asm("fma.rn.f32x2 %0, %1, %2, %0;" : "+l"(accB) : "l"(wpk[2*k2+1]), "l"(hp.y));
        }
        unsigned long long acc;
        asm("add.rn.f32x2 %0, %1, %2;" : "=l"(acc) : "l"(accA), "l"(accB));
        float a0, a1;
        asm("mov.b64 {%0,%1}, %2;" : "=f"(a0), "=f"(a1) : "l"(acc));

        float v0, v1;
        if (gtype == 2){ v0 = tanh_f(a0);    v1 = tanh_f(a1); }
        else           { v0 = sigmoid_f(a0); v1 = sigmoid_f(a1); }
        g_s[0][tid] = v0; g_s[1][tid] = v1;
        __syncthreads();

        if (tid < 128){
            const int row = tid >> 6, j = tid & 63;
            float iv = g_s[row][j],       fv = g_s[row][64+j];
            float gv = g_s[row][128+j],   ov = g_s[row][192+j];
            float cc = fmaf(fv, c_s[row][j], iv*gv);
            c_s[row][j] = cc;
            float h = ov * tanh_f(cc);
            ((float*)&h_s[j])[row] = h;
            h_out[(((size_t)(b0+row))*T_ + t)*H_ + j] = h;
        }
        __syncthreads();
        p0 = q0; p1 = q1; q0 = r0; q1 = r1;
    }
}

// ---------------------------------------------------------------- FC head
__global__ void fc_kernel(const float* __restrict__ h, const float* __restrict__ fw,
                          const float* __restrict__ fb, float* __restrict__ out)
{
    size_t m = (size_t)blockIdx.x * blockDim.x + threadIdx.x;
    const float4* hv = (const float4*)(h + m * H_);
    float acc = 0.f;
    #pragma unroll
    for (int i = 0; i < H_/4; i++){
        float4 a = hv[i];
        float4 w = __ldg(((const float4*)fw) + i);
        acc = fmaf(a.x, w.x, fmaf(a.y, w.y, fmaf(a.z, w.z, fmaf(a.w, w.w, acc))));
    }
    out[m] = acc + __ldg(fb);
}

// ---------------------------------------------------------------- launch
extern "C" void kernel_launch(void* const* d_in, const int* in_sizes, int n_in,
                              void* d_out, int out_size)
{
    const float* x     = (const float*)d_in[0];
    const float* w_ih0 = (const float*)d_in[1];
    const float* w_hh0 = (const float*)d_in[2];
    const float* b_ih0 = (const float*)d_in[3];
    const float* b_hh0 = (const float*)d_in[4];
    const float* w_ih1 = (const float*)d_in[5];
    const float* w_hh1 = (const float*)d_in[6];
    const float* b_ih1 = (const float*)d_in[7];
    const float* b_hh1 = (const float*)d_in[8];
    const float* w_ih2 = (const float*)d_in[9];
    const float* w_hh2 = (const float*)d_in[10];
    const float* b_ih2 = (const float*)d_in[11];
    const float* b_hh2 = (const float*)d_in[12];
    const float* fc_w  = (const float*)d_in[13];
    const float* fc_b  = (const float*)d_in[14];
    float* out = (float*)d_out;

    float *pre, *h0, *h1;
    cudaGetSymbolAddress((void**)&pre, g_pre);
    cudaGetSymbolAddress((void**)&h0,  g_h0);
    cudaGetSymbolAddress((void**)&h1,  g_h1);

    const int smem128 = (128+256)*(128+4)*4 + 256*4;   // ~204 KB
    const int smem64  = (128+256)*(64+4)*4  + 256*4;   // ~105 KB
    cudaFuncSetAttribute(gemm_pre<128>, cudaFuncAttributeMaxDynamicSharedMemorySize, smem128);
    cudaFuncSetAttribute(gemm_pre<64>,  cudaFuncAttributeMaxDynamicSharedMemorySize, smem64);

    gemm_pre<128><<<M_/128, 256, smem128>>>(x,  w_ih0, b_ih0, b_hh0, pre);
    lstm_scan    <<<B_/2,   256>>>(pre, w_hh0, h0);
    gemm_pre<64> <<<M_/128, 256, smem64 >>>(h0, w_ih1, b_ih1, b_hh1, pre);
    lstm_scan    <<<B_/2,   256>>>(pre, w_hh1, h1);
    gemm_pre<64> <<<M_/128, 256, smem64 >>>(h1, w_ih2, b_ih2, b_hh2, pre);
    lstm_scan    <<<B_/2,   256>>>(pre, w_hh2, h0);
    fc_kernel    <<<M_/256, 256>>>(h0, fc_w, fc_b, out);
}